// round 9
// baseline (speedup 1.0000x reference)
#include <cuda_runtime.h>
#include <cuda_fp16.h>
#include <cstdint>

// DepthAwareConv2d as fp16 mma.sync (m16n8k16, fp32 accum) implicit GEMM.
// R9: 64x64 warp tiles (CTA = 128 o x 256 px = two image rows).
// B layout fix vs R8: row stride RSB=136 (16B-aligned cp.async) with an
// 8-word skew per cpair block (CPS = 4*RSB + 8 = 552) so warp B-reads hit
// banks {0,8,16,24}+{0..7} -> conflict-free AND aligned.

#define Nn 4
#define Cc 128
#define Oo 256
#define Hh 128
#define Ww 128
#define CG 16                // channels per group (= MMA K)
#define NCG (Cc / CG)        // 8
#define RSB 136              // B row stride in b32 (16B-aligned)
#define CPS 552              // cpair block stride in b32 (= 4*RSB + 8 skew)

// A image per (o-tile 128, c-group): [tap 9][mt 8][lane 32][r 4] b32
#define ASZ 9216
// B image per c-group: 8 cpair blocks x CPS b32
#define BSZ (8 * CPS)        // 4416 b32

__device__ uint32_t g_xdt2[Nn * (Cc / 2) * Hh * Ww];   // half2(xd[2c], xd[2c+1])
__device__ uint32_t g_wta2[2 * NCG * ASZ];             // fragment-major fp16 weights

// ----------------------------- helpers --------------------------------------
__device__ __forceinline__ void cp_async16(uint32_t dst, const void* src) {
    asm volatile("cp.async.ca.shared.global [%0], [%1], 16;"
                 :: "r"(dst), "l"(src) : "memory");
}
__device__ __forceinline__ void cp_async16z(uint32_t dst, const void* src, uint32_t sz) {
    asm volatile("cp.async.ca.shared.global [%0], [%1], 16, %2;"
                 :: "r"(dst), "l"(src), "r"(sz) : "memory");
}
__device__ __forceinline__ void cp_commit() {
    asm volatile("cp.async.commit_group;" ::: "memory");
}
template <int N>
__device__ __forceinline__ void cp_wait() {
    asm volatile("cp.async.wait_group %0;" :: "n"(N) : "memory");
}
__device__ __forceinline__ uint32_t lds32(uint32_t addr) {
    uint32_t v;
    asm volatile("ld.shared.b32 %0, [%1];" : "=r"(v) : "r"(addr));
    return v;
}
__device__ __forceinline__ void mma_f16(float& c0, float& c1, float& c2, float& c3,
                                        uint32_t a0, uint32_t a1, uint32_t a2, uint32_t a3,
                                        uint32_t b0, uint32_t b1) {
    asm("mma.sync.aligned.m16n8k16.row.col.f32.f16.f16.f32 "
        "{%0,%1,%2,%3}, {%4,%5,%6,%7}, {%8,%9}, {%0,%1,%2,%3};"
        : "+f"(c0), "+f"(c1), "+f"(c2), "+f"(c3)
        : "r"(a0), "r"(a1), "r"(a2), "r"(a3), "r"(b0), "r"(b1));
}
__device__ __forceinline__ uint32_t pack_h2(float lo, float hi) {
    __half2 h = __floats2half2_rn(lo, hi);
    return *reinterpret_cast<uint32_t*>(&h);
}

// ------------------------------ prep kernels --------------------------------
// g_xdt2 b32 layout: [n][cp=64][y][x]; b32 = half2(xd[2cp], xd[2cp+1]).
__global__ void prep_xd2_kernel(const float* __restrict__ x, const float* __restrict__ dep) {
    const int i = (blockIdx.x * 256 + threadIdx.x) * 4;
    const int n  = i >> 20;
    const int cp = (i >> 14) & 63;
    const int hw = i & 16383;
    const float4 x0 = *reinterpret_cast<const float4*>(x + (((size_t)(n * Cc + 2 * cp)) << 14) + hw);
    const float4 x1 = *reinterpret_cast<const float4*>(x + (((size_t)(n * Cc + 2 * cp + 1)) << 14) + hw);
    const float4 dv = *reinterpret_cast<const float4*>(dep + ((size_t)n << 14) + hw);
    uint4 r;
    r.x = pack_h2(x0.x * dv.x, x1.x * dv.x);
    r.y = pack_h2(x0.y * dv.y, x1.y * dv.y);
    r.z = pack_h2(x0.z * dv.z, x1.z * dv.z);
    r.w = pack_h2(x0.w * dv.w, x1.w * dv.w);
    *reinterpret_cast<uint4*>(g_xdt2 + i) = r;
}

// g_wta2[(ot*NCG+cg)*ASZ + ((tap*8+mt)*32+lane)*4 + r]:
//   o = ot*128 + mt*16 + (r&1)*8 + lane/4
//   c = cg*16 + (lane%4)*2 + (r>>1)*8 + {0,1}
__global__ void prep_wa2_kernel(const float* __restrict__ w) {
    const int i = blockIdx.x * 256 + threadIdx.x;
    if (i >= 2 * NCG * ASZ) return;
    const int r    = i & 3;
    const int lane = (i >> 2) & 31;
    const int mt   = (i >> 7) & 7;
    const int tap  = (i >> 10) % 9;
    const int rest = i / ASZ;
    const int cg   = rest & (NCG - 1);
    const int ot   = rest >> 3;
    const int o  = ot * 128 + mt * 16 + (r & 1) * 8 + (lane >> 2);
    const int cb = cg * CG + (lane & 3) * 2 + ((r >> 1) << 3);
    g_wta2[i] = pack_h2(w[(o * Cc + cb) * 9 + tap], w[(o * Cc + cb + 1) * 9 + tap]);
}

// ------------------------------- main kernel --------------------------------
// grid (Nn*Hh/2, 2), 256 threads. CTA: M=128 o, N=256 px (rows ybase, ybase+1).
// Warp (wid = warpM*4 + warpN): warpM -> 64 o's, warpN -> (row = warpN>>1,
// half-row x-chunk = (warpN&1)*64). B: 4 staged input rows ybase-1..ybase+2
// per cpair block at stride CPS. Row layout: px x at b32 [4..131],
// halo x=-1 at [3], x=128 at [132]; slots {0,1,2,3,132..135} zeroed once.
__global__ __launch_bounds__(256)
void conv_f16_mma64_kernel(const float* __restrict__ bias, float* __restrict__ out)
{
    extern __shared__ uint32_t smem[];
    const uint32_t sAb = (uint32_t)__cvta_generic_to_shared(smem);
    const uint32_t sBb = sAb + 2 * ASZ * 4;

    const int tid   = threadIdx.x;
    const int lane  = tid & 31;
    const int wid   = tid >> 5;
    const int warpM = wid >> 2;                  // 0..1
    const int warpN = wid & 3;                   // 0..3
    const int wrow  = warpN >> 1;                // output row within pair
    const int wxb   = (warpN & 1) * 64;          // x-chunk base

    const int pix2  = blockIdx.x * 256;
    const int n     = pix2 >> 14;
    const int ybase = (pix2 >> 7) & (Hh - 1);    // even
    const int ot    = blockIdx.y;
    const int oBase = ot * 128;

    const uint32_t* xsrc = g_xdt2 + ((size_t)n << 20);
    const uint32_t* asrc = g_wta2 + (size_t)(ot * NCG) * ASZ;

    // ---- zero pads in both B buffers: 2 bufs x 8 cpairs x 4 rows x 8 slots ----
    for (int idx = tid; idx < 512; idx += 256) {
        const int buf = idx >> 8, rem = idx & 255;
        const int row = rem >> 3, p = rem & 7;     // row = cp*4 + rr
        const int cp = row >> 2, rr = row & 3;
        smem[2 * ASZ + buf * BSZ + cp * CPS + rr * RSB + (p < 4 ? p : 128 + p)] = 0u;
    }

    // ---- staging: one c-group into buffer `buf` (all 16B cp.async) ----
    auto stage = [&](int cg, int buf) {
        const uint32_t* as = asrc + (size_t)cg * ASZ;
        const uint32_t dA = sAb + buf * (ASZ * 4);
        #pragma unroll
        for (int i = 0; i < 9; i++) {                    // A: 2304 x 16B, linear
            const int idx = i * 256 + tid;
            cp_async16(dA + idx * 16, as + idx * 4);
        }
        const uint32_t dB = sBb + buf * (BSZ * 4);
        #pragma unroll
        for (int i = 0; i < 4; i++) {                    // B: 1024 x 16B
            const int idx = i * 256 + tid;
            const int pair = idx >> 5, seg = idx & 31;   // pair = cp*4 + rr
            const int cp = pair >> 2, rr = pair & 3;
            const int yy = ybase + rr - 1;
            const bool inb = (unsigned)yy < (unsigned)Hh;
            const int yc = inb ? yy : 0;
            const uint32_t* src = xsrc + (((size_t)(cg * 8 + cp)) << 14) + (yc << 7) + seg * 4;
            cp_async16z(dB + (cp * CPS + rr * RSB + 4 + seg * 4) * 4, src, inb ? 16u : 0u);
        }
        cp_commit();
    };

    float acc[4][8][4];
    #pragma unroll
    for (int m = 0; m < 4; m++)
        #pragma unroll
        for (int j = 0; j < 8; j++)
            #pragma unroll
            for (int r = 0; r < 4; r++) acc[m][j][r] = 0.0f;

    // per-thread B base: cpair = lane%4, row = wrow, px = wxb + lane/4, x shift -1
    const uint32_t bTh = ((lane & 3) * CPS + wrow * RSB + 4 + wxb + (lane >> 2) - 1) * 4;

    stage(0, 0);

    for (int cg = 0; cg < NCG; ++cg) {
        const int buf = cg & 1;
        if (cg + 1 < NCG) { stage(cg + 1, buf ^ 1); cp_wait<1>(); }
        else             { cp_wait<0>(); }
        __syncthreads();

        const uint4* fA = reinterpret_cast<const uint4*>(smem) + buf * (ASZ / 4);
        const uint32_t bBase0 = sBb + buf * (BSZ * 4) + bTh;      // cpairs 0..3
        const uint32_t bBase1 = bBase0 + 4 * CPS * 4;             // cpairs 4..7

        #pragma unroll
        for (int tap = 0; tap < 9; tap++) {
            const int dy = tap / 3, dx = tap - dy * 3;
            const uint32_t doff = (dy * RSB + dx) * 4;

            uint32_t b0[8], b1[8];
            #pragma unroll
            for (int j = 0; j < 8; j++) {
                b0[j] = lds32(bBase0 + doff + j * 32);   // +8 px per n-subtile
                b1[j] = lds32(bBase1 + doff + j * 32);
            }
            uint4 av[4];
            #pragma unroll
            for (int m = 0; m < 4; m++)
                av[m] = fA[(tap * 8 + warpM * 4 + m) * 32 + lane];

            #pragma unroll
            for (int m = 0; m < 4; m++)
                #pragma unroll
                for (int j = 0; j < 8; j++)
                    mma_f16(acc[m][j][0], acc[m][j][1], acc[m][j][2], acc[m][j][3],
                            av[m].x, av[m].y, av[m].z, av[m].w, b0[j], b1[j]);
        }
        __syncthreads();   // before next stage overwrites this buffer
    }

    // ---- epilogue: +bias, direct STG.64 ----
    const int g = lane >> 2, t = lane & 3;
    const int yout = ybase + wrow;
    #pragma unroll
    for (int m = 0; m < 4; m++) {
        const int oLo = oBase + warpM * 64 + m * 16 + g;
        const float bLo = bias[oLo], bHi = bias[oLo + 8];
        const size_t rowLo = (((size_t)(n * Oo + oLo))     << 14) + (yout << 7);
        const size_t rowHi = (((size_t)(n * Oo + oLo + 8)) << 14) + (yout << 7);
        #pragma unroll
        for (int j = 0; j < 8; j++) {
            const int xb = wxb + j * 8 + 2 * t;
            float2 lo = make_float2(acc[m][j][0] + bLo, acc[m][j][1] + bLo);
            float2 hi = make_float2(acc[m][j][2] + bHi, acc[m][j][3] + bHi);
            *reinterpret_cast<float2*>(out + rowLo + xb) = lo;
            *reinterpret_cast<float2*>(out + rowHi + xb) = hi;
        }
    }
}

// ------------------------------- launcher -----------------------------------
extern "C" void kernel_launch(void* const* d_in, const int* in_sizes, int n_in,
                              void* d_out, int out_size)
{
    const float* x    = (const float*)d_in[0];
    const float* dep  = (const float*)d_in[1];
    // d_in[2] = camera_params (unused by the math)
    const float* w    = (const float*)d_in[3];
    const float* bias = (const float*)d_in[4];
    float* out = (float*)d_out;

    constexpr int SMEM_BYTES = (2 * ASZ + 2 * BSZ) * 4;   // 109,056 B

    static bool attr_set = false;
    if (!attr_set) {
        cudaFuncSetAttribute(conv_f16_mma64_kernel,
                             cudaFuncAttributeMaxDynamicSharedMemorySize, SMEM_BYTES);
        attr_set = true;
    }

    prep_wa2_kernel<<<(2 * NCG * ASZ + 255) / 256, 256>>>(w);
    prep_xd2_kernel<<<(Nn * (Cc / 2) * Hh * Ww / 4 + 255) / 256, 256>>>(x, dep);

    dim3 grid(Nn * Hh / 2, 2, 1);   // 512 CTAs
    conv_f16_mma64_kernel<<<grid, 256, SMEM_BYTES>>>(bias, out);
}

// round 10
// speedup vs baseline: 1.0889x; 1.0889x over previous
#include <cuda_runtime.h>
#include <cuda_fp16.h>
#include <cstdint>

// DepthAwareConv2d as fp16 mma.sync (m16n8k16, fp32 accum) implicit GEMM.
// R10 = R7 base (64x32 warp tiles, 2 CTA/SM) + merged prep launch +
// cp.async.cg staging (L2-only) + final-iteration sync elision.

#define Nn 4
#define Cc 128
#define Oo 256
#define Hh 128
#define Ww 128
#define CG 16                // channels per group (= MMA K)
#define NCG (Cc / CG)        // 8
#define RS2 136              // B row stride in b32 units (conflict-free)

// A image per (o-tile 128, c-group): [tap 9][mt 8][lane 32][r 4] b32
#define ASZ 9216
// B image per c-group: 8 cpairs x 3 rows x RS2 b32
#define BSZ (8 * 3 * RS2)    // 3264 b32

// grid split for the merged prep kernel
#define GXD (Nn * (Cc / 2) * Hh * Ww / 4 / 256)   // 4096 blocks
#define GWA ((2 * NCG * ASZ + 255) / 256)         // 576 blocks

__device__ uint32_t g_xdt2[Nn * (Cc / 2) * Hh * Ww];   // half2(xd[2c], xd[2c+1])
__device__ uint32_t g_wta2[2 * NCG * ASZ];             // fragment-major fp16 weights

// ----------------------------- helpers --------------------------------------
__device__ __forceinline__ void cp_async16(uint32_t dst, const void* src) {
    asm volatile("cp.async.cg.shared.global [%0], [%1], 16;"
                 :: "r"(dst), "l"(src) : "memory");
}
__device__ __forceinline__ void cp_async16z(uint32_t dst, const void* src, uint32_t sz) {
    asm volatile("cp.async.cg.shared.global [%0], [%1], 16, %2;"
                 :: "r"(dst), "l"(src), "r"(sz) : "memory");
}
__device__ __forceinline__ void cp_commit() {
    asm volatile("cp.async.commit_group;" ::: "memory");
}
template <int N>
__device__ __forceinline__ void cp_wait() {
    asm volatile("cp.async.wait_group %0;" :: "n"(N) : "memory");
}
__device__ __forceinline__ uint32_t lds32(uint32_t addr) {
    uint32_t v;
    asm volatile("ld.shared.b32 %0, [%1];" : "=r"(v) : "r"(addr));
    return v;
}
__device__ __forceinline__ void mma_f16(float& c0, float& c1, float& c2, float& c3,
                                        uint32_t a0, uint32_t a1, uint32_t a2, uint32_t a3,
                                        uint32_t b0, uint32_t b1) {
    asm("mma.sync.aligned.m16n8k16.row.col.f32.f16.f16.f32 "
        "{%0,%1,%2,%3}, {%4,%5,%6,%7}, {%8,%9}, {%0,%1,%2,%3};"
        : "+f"(c0), "+f"(c1), "+f"(c2), "+f"(c3)
        : "r"(a0), "r"(a1), "r"(a2), "r"(a3), "r"(b0), "r"(b1));
}
__device__ __forceinline__ uint32_t pack_h2(float lo, float hi) {
    __half2 h = __floats2half2_rn(lo, hi);
    return *reinterpret_cast<uint32_t*>(&h);
}

// --------------------------- merged prep kernel ------------------------------
// Blocks [0, GXD): xd pack.  Blocks [GXD, GXD+GWA): weight permute.
// g_xdt2 b32 layout: [n][cp=64][y][x]; b32 = half2(xd[2cp], xd[2cp+1]).
// g_wta2[(ot*NCG+cg)*ASZ + ((tap*8+mt)*32+lane)*4 + r]:
//   o = ot*128 + mt*16 + (r&1)*8 + lane/4
//   c = cg*16 + (lane%4)*2 + (r>>1)*8 + {0,1}
__global__ void prep_all_kernel(const float* __restrict__ x,
                                const float* __restrict__ dep,
                                const float* __restrict__ w)
{
    if (blockIdx.x < GXD) {
        const int i = (blockIdx.x * 256 + threadIdx.x) * 4;
        const int n  = i >> 20;
        const int cp = (i >> 14) & 63;
        const int hw = i & 16383;
        const float4 x0 = *reinterpret_cast<const float4*>(x + (((size_t)(n * Cc + 2 * cp)) << 14) + hw);
        const float4 x1 = *reinterpret_cast<const float4*>(x + (((size_t)(n * Cc + 2 * cp + 1)) << 14) + hw);
        const float4 dv = *reinterpret_cast<const float4*>(dep + ((size_t)n << 14) + hw);
        uint4 r;
        r.x = pack_h2(x0.x * dv.x, x1.x * dv.x);
        r.y = pack_h2(x0.y * dv.y, x1.y * dv.y);
        r.z = pack_h2(x0.z * dv.z, x1.z * dv.z);
        r.w = pack_h2(x0.w * dv.w, x1.w * dv.w);
        *reinterpret_cast<uint4*>(g_xdt2 + i) = r;
    } else {
        const int i = (blockIdx.x - GXD) * 256 + threadIdx.x;
        if (i >= 2 * NCG * ASZ) return;
        const int r    = i & 3;
        const int lane = (i >> 2) & 31;
        const int mt   = (i >> 7) & 7;
        const int tap  = (i >> 10) % 9;
        const int rest = i / ASZ;
        const int cg   = rest & (NCG - 1);
        const int ot   = rest >> 3;
        const int o  = ot * 128 + mt * 16 + (r & 1) * 8 + (lane >> 2);
        const int cb = cg * CG + (lane & 3) * 2 + ((r >> 1) << 3);
        g_wta2[i] = pack_h2(w[(o * Cc + cb) * 9 + tap], w[(o * Cc + cb + 1) * 9 + tap]);
    }
}

// ------------------------------- main kernel --------------------------------
// grid (Nn*Hh, 2), 256 threads. CTA: M=128 o, N=128 px (one image row), all K.
// SMEM: sA[2][ASZ] b32 then sB[2][BSZ] b32. B row: data x at b32 [4..131],
// halo x=-1 at [3], x=128 at [132]; filler [0..2],[133..135] zeroed once.
__global__ __launch_bounds__(256, 2)
void conv_f16_mma_kernel(const float* __restrict__ bias, float* __restrict__ out)
{
    extern __shared__ uint32_t smem[];
    const uint32_t sAb = (uint32_t)__cvta_generic_to_shared(smem);
    const uint32_t sBb = sAb + 2 * ASZ * 4;

    const int tid   = threadIdx.x;
    const int lane  = tid & 31;
    const int wid   = tid >> 5;
    const int warpM = wid >> 2;                  // 0..1
    const int warpN = wid & 3;                   // 0..3

    const int pix = blockIdx.x * 128;
    const int n   = pix >> 14;
    const int y   = (pix >> 7) & (Hh - 1);
    const int ot  = blockIdx.y;
    const int oBase = ot * 128;

    const uint32_t* xsrc = g_xdt2 + ((size_t)n << 20);
    const uint32_t* asrc = g_wta2 + (size_t)(ot * NCG) * ASZ;

    // ---- zero halo/filler pads in both B buffers (2 x 24 rows x 8 slots) ----
    for (int idx = tid; idx < 384; idx += 256) {
        const int buf = idx / 192, rem = idx % 192;
        const int row = rem >> 3, p = rem & 7;
        smem[2 * ASZ + buf * BSZ + row * RS2 + (p < 4 ? p : 128 + p)] = 0u;
    }

    // ---- staging: one c-group into buffer `buf` (all 16B cp.async.cg) ----
    auto stage = [&](int cg, int buf) {
        const uint32_t* as = asrc + (size_t)cg * ASZ;
        const uint32_t dA = sAb + buf * (ASZ * 4);
        #pragma unroll
        for (int i = 0; i < 9; i++) {                    // A: 2304 x 16B, linear
            const int idx = i * 256 + tid;
            cp_async16(dA + idx * 16, as + idx * 4);
        }
        const uint32_t dB = sBb + buf * (BSZ * 4);
        #pragma unroll
        for (int i = 0; i < 3; i++) {                    // B: 768 x 16B, rows
            const int idx = i * 256 + tid;
            const int pair = idx >> 5, seg = idx & 31;   // pair = cpair*3 + row
            const int cp = pair / 3, rr = pair - cp * 3;
            const int yy = y + rr - 1;
            const bool inb = (unsigned)yy < (unsigned)Hh;
            const int yc = inb ? yy : 0;
            const uint32_t* src = xsrc + (((size_t)(cg * 8 + cp)) << 14) + (yc << 7) + seg * 4;
            cp_async16z(dB + (pair * RS2 + 4 + seg * 4) * 4, src, inb ? 16u : 0u);
        }
        cp_commit();
    };

    float acc[4][4][4];
    #pragma unroll
    for (int m = 0; m < 4; m++)
        #pragma unroll
        for (int j = 0; j < 4; j++)
            #pragma unroll
            for (int r = 0; r < 4; r++) acc[m][j][r] = 0.0f;

    // per-thread B base: cpair = lane%4, pixel = warpN*32 + lane/4, x shift -1
    const uint32_t bTh = ((lane & 3) * 3 * RS2 + 4 + warpN * 32 + (lane >> 2) - 1) * 4;

    stage(0, 0);

    for (int cg = 0; cg < NCG; ++cg) {
        const int buf = cg & 1;
        if (cg + 1 < NCG) { stage(cg + 1, buf ^ 1); cp_wait<1>(); }
        else             { cp_wait<0>(); }
        __syncthreads();

        const uint4* fA = reinterpret_cast<const uint4*>(smem) + buf * (ASZ / 4);
        const uint32_t bBase0 = sBb + buf * (BSZ * 4) + bTh;      // cpair = lane%4
        const uint32_t bBase1 = bBase0 + 4 * 3 * RS2 * 4;         // cpair + 4

        #pragma unroll
        for (int tap = 0; tap < 9; tap++) {
            const int dy = tap / 3, dx = tap - dy * 3;
            const uint32_t doff = (dy * RS2 + dx) * 4;

            uint32_t b0[4], b1[4];
            #pragma unroll
            for (int j = 0; j < 4; j++) {
                b0[j] = lds32(bBase0 + doff + j * 32);   // +8 px per n-subtile
                b1[j] = lds32(bBase1 + doff + j * 32);
            }
            uint4 av[4];
            #pragma unroll
            for (int m = 0; m < 4; m++)
                av[m] = fA[(tap * 8 + warpM * 4 + m) * 32 + lane];

            #pragma unroll
            for (int m = 0; m < 4; m++)
                #pragma unroll
                for (int j = 0; j < 4; j++)
                    mma_f16(acc[m][j][0], acc[m][j][1], acc[m][j][2], acc[m][j][3],
                            av[m].x, av[m].y, av[m].z, av[m].w, b0[j], b1[j]);
        }
        // protect buffer reuse by the NEXT stage; no next stage on last iter
        if (cg + 2 < NCG) __syncthreads();
    }

    // ---- epilogue: +bias, direct STG.64 (registers only; no smem hazard) ----
    const int g = lane >> 2, t = lane & 3;
    #pragma unroll
    for (int m = 0; m < 4; m++) {
        const int oLo = oBase + warpM * 64 + m * 16 + g;
        const float bLo = bias[oLo], bHi = bias[oLo + 8];
        const size_t rowLo = (((size_t)(n * Oo + oLo))     << 14) + (y << 7);
        const size_t rowHi = (((size_t)(n * Oo + oLo + 8)) << 14) + (y << 7);
        #pragma unroll
        for (int j = 0; j < 4; j++) {
            const int xb = warpN * 32 + j * 8 + 2 * t;
            float2 lo = make_float2(acc[m][j][0] + bLo, acc[m][j][1] + bLo);
            float2 hi = make_float2(acc[m][j][2] + bHi, acc[m][j][3] + bHi);
            *reinterpret_cast<float2*>(out + rowLo + xb) = lo;
            *reinterpret_cast<float2*>(out + rowHi + xb) = hi;
        }
    }
}

// ------------------------------- launcher -----------------------------------
extern "C" void kernel_launch(void* const* d_in, const int* in_sizes, int n_in,
                              void* d_out, int out_size)
{
    const float* x    = (const float*)d_in[0];
    const float* dep  = (const float*)d_in[1];
    // d_in[2] = camera_params (unused by the math)
    const float* w    = (const float*)d_in[3];
    const float* bias = (const float*)d_in[4];
    float* out = (float*)d_out;

    constexpr int SMEM_BYTES = (2 * ASZ + 2 * BSZ) * 4;   // 99,840 B

    static bool attr_set = false;
    if (!attr_set) {
        cudaFuncSetAttribute(conv_f16_mma_kernel,
                             cudaFuncAttributeMaxDynamicSharedMemorySize, SMEM_BYTES);
        attr_set = true;
    }

    prep_all_kernel<<<GXD + GWA, 256>>>(x, dep, w);

    dim3 grid(Nn * Hh, 2, 1);   // 1024 CTAs
    conv_f16_mma_kernel<<<grid, 256, SMEM_BYTES>>>(bias, out);
}